// round 16
// baseline (speedup 1.0000x reference)
#include <cuda_runtime.h>
#include <cstdint>
#include <math.h>

#define HIDN 4096
#define NH   32
#define NKV  8
#define HD   128
#define BB   4
#define QL   1024
#define PAST 1024
#define SKV  2048
#define MROWS (BB*QL)   /* 4096 */

// -------- scratch (device globals; no allocation allowed) --------
__device__ float g_q[(size_t)MROWS * HIDN];        // tf32-rounded
__device__ float g_k[(size_t)MROWS * (NKV * HD)];  // tf32-rounded
__device__ float g_v[(size_t)MROWS * (NKV * HD)];  // tf32-rounded
__device__ float g_att[(size_t)MROWS * HIDN];      // tf32-rounded
// pre-rounded copies of harness inputs
__device__ float t_hid[(size_t)MROWS * HIDN];
__device__ float t_wq[(size_t)HIDN * HIDN];
__device__ float t_wk[(size_t)(NKV * HD) * HIDN];
__device__ float t_wv[(size_t)(NKV * HD) * HIDN];
__device__ float t_wo[(size_t)HIDN * HIDN];
__device__ float t_pk[(size_t)BB * NKV * PAST * HD];
__device__ float t_pv[(size_t)BB * NKV * PAST * HD];

// ======================================================================
// helpers
// ======================================================================
__device__ __forceinline__ uint32_t smem_u32(const void* p) {
    uint32_t a;
    asm("{ .reg .u64 t; cvta.to.shared.u64 t, %1; cvt.u32.u64 %0, t; }" : "=r"(a) : "l"(p));
    return a;
}

__device__ __forceinline__ void cp_async16(uint32_t s, const void* g) {
    asm volatile("cp.async.cg.shared.global [%0], [%1], 16;" :: "r"(s), "l"(g) : "memory");
}

__device__ __forceinline__ uint32_t f2tf32(float x) {
    uint32_t r;
    asm("cvt.rna.tf32.f32 %0, %1;" : "=r"(r) : "f"(x));
    return r;
}
__device__ __forceinline__ float f2tf32f(float x) { return __uint_as_float(f2tf32(x)); }

__device__ __forceinline__ void mma_tf32_16n8k8(float* c, const uint32_t* a, const uint32_t* b) {
    asm volatile(
        "mma.sync.aligned.m16n8k8.row.col.f32.tf32.tf32.f32 "
        "{%0,%1,%2,%3}, {%4,%5,%6,%7}, {%8,%9}, {%0,%1,%2,%3};"
        : "+f"(c[0]), "+f"(c[1]), "+f"(c[2]), "+f"(c[3])
        : "r"(a[0]), "r"(a[1]), "r"(a[2]), "r"(a[3]), "r"(b[0]), "r"(b[1]));
}

// ======================================================================
// elementwise RNA-tf32 pre-rounding pass
// ======================================================================
__global__ __launch_bounds__(256) void round_tf32(
    const float4* __restrict__ in, float4* __restrict__ out, int n4)
{
    int i = blockIdx.x * blockDim.x + threadIdx.x;
    if (i < n4) {
        float4 v = in[i];
        float4 o = {f2tf32f(v.x), f2tf32f(v.y), f2tf32f(v.z), f2tf32f(v.w)};
        out[i] = o;
    }
}

// ======================================================================
// tf32 mma.sync GEMM-NT on pre-rounded operands (unchanged, passing)
// ======================================================================
#define SA 20

__global__ __launch_bounds__(256, 2) void gemm_mma(
    const float* __restrict__ A, const float* __restrict__ W,
    const float* __restrict__ bias, float* __restrict__ C,
    int ldc, int K, float alpha, int rnd)
{
    __shared__ float As[2][128][SA];
    __shared__ float Bs[2][128][SA];

    const int tid  = threadIdx.x;
    const int lane = tid & 31, w = tid >> 5;
    const int g = lane >> 2, t = lane & 3;
    const int wm = (w & 1) * 64, wn = (w >> 1) * 32;
    const int bm = blockIdx.y * 128, bn = blockIdx.x * 128;

    const int r  = tid >> 2;
    const int c4 = (tid & 3) << 2;

    const float* aBase = A + (size_t)(bm + r) * K + c4;
    const float* bBase = W + (size_t)(bn + r) * K + c4;
    const size_t rowskip = (size_t)64 * K;

    float acc[4][4][4];
#pragma unroll
    for (int mi = 0; mi < 4; ++mi)
#pragma unroll
        for (int ni = 0; ni < 4; ++ni)
#pragma unroll
            for (int e = 0; e < 4; ++e) acc[mi][ni][e] = 0.f;

    const int kiters = K >> 4;

    {
        cp_async16(smem_u32(&As[0][r][c4]), aBase);
        cp_async16(smem_u32(&As[0][r + 64][c4]), aBase + rowskip);
        cp_async16(smem_u32(&Bs[0][r][c4]), bBase);
        cp_async16(smem_u32(&Bs[0][r + 64][c4]), bBase + rowskip);
        asm volatile("cp.async.commit_group;" ::: "memory");
    }

    for (int it = 0; it < kiters; ++it) {
        const int buf = it & 1;
        if (it + 1 < kiters) {
            const float* ag = aBase + (size_t)(it + 1) * 16;
            const float* bg = bBase + (size_t)(it + 1) * 16;
            cp_async16(smem_u32(&As[buf ^ 1][r][c4]), ag);
            cp_async16(smem_u32(&As[buf ^ 1][r + 64][c4]), ag + rowskip);
            cp_async16(smem_u32(&Bs[buf ^ 1][r][c4]), bg);
            cp_async16(smem_u32(&Bs[buf ^ 1][r + 64][c4]), bg + rowskip);
            asm volatile("cp.async.commit_group;" ::: "memory");
            asm volatile("cp.async.wait_group 1;" ::: "memory");
        } else {
            asm volatile("cp.async.wait_group 0;" ::: "memory");
        }
        __syncthreads();

#pragma unroll
        for (int ks = 0; ks < 16; ks += 8) {
            uint32_t af[4][4], bf[4][2];
#pragma unroll
            for (int mi = 0; mi < 4; ++mi) {
                const int mr = wm + 16 * mi + g;
                af[mi][0] = __float_as_uint(As[buf][mr][ks + t]);
                af[mi][1] = __float_as_uint(As[buf][mr + 8][ks + t]);
                af[mi][2] = __float_as_uint(As[buf][mr][ks + t + 4]);
                af[mi][3] = __float_as_uint(As[buf][mr + 8][ks + t + 4]);
            }
#pragma unroll
            for (int ni = 0; ni < 4; ++ni) {
                const int nr = wn + 8 * ni + g;
                bf[ni][0] = __float_as_uint(Bs[buf][nr][ks + t]);
                bf[ni][1] = __float_as_uint(Bs[buf][nr][ks + t + 4]);
            }
#pragma unroll
            for (int mi = 0; mi < 4; ++mi)
#pragma unroll
                for (int ni = 0; ni < 4; ++ni)
                    mma_tf32_16n8k8(acc[mi][ni], af[mi], bf[ni]);
        }
        __syncthreads();
    }

#pragma unroll
    for (int mi = 0; mi < 4; ++mi) {
        const int row0 = bm + wm + 16 * mi + g;
#pragma unroll
        for (int ni = 0; ni < 4; ++ni) {
            const int col = bn + wn + 8 * ni + 2 * t;
            const float b0 = bias[col], b1 = bias[col + 1];
            float2 v0, v1;
            v0.x = alpha * (acc[mi][ni][0] + b0);
            v0.y = alpha * (acc[mi][ni][1] + b1);
            v1.x = alpha * (acc[mi][ni][2] + b0);
            v1.y = alpha * (acc[mi][ni][3] + b1);
            if (rnd) {
                v0.x = f2tf32f(v0.x); v0.y = f2tf32f(v0.y);
                v1.x = f2tf32f(v1.x); v1.y = f2tf32f(v1.y);
            }
            *(float2*)&C[(size_t)row0 * ldc + col]       = v0;
            *(float2*)&C[(size_t)(row0 + 8) * ldc + col] = v1;
        }
    }
}

// ======================================================================
// Tensor-core flash attention, 512 threads / 16 warps (4 per SMSP).
// Warp grid 8m x 2n: S warp tile 16x32, PV warp tile 16x64.
// Cross-warp softmax via smem partial-max; per-warp partial l combined
// once at the end. cp.async K double-buffer / V single-buffer pipeline.
// ======================================================================
#define SQ 132
#define SV 136
#define SP 68
#define NKT (SKV / 64)
#define ATTN2_FLOATS (128*SQ + 2*64*SQ + 64*SV + 128*SP + 256)
#define ATTN2_SMEM (ATTN2_FLOATS * 4)   /* 205824 B */

__global__ __launch_bounds__(512, 1) void attn_mma(
    const float* __restrict__ pastk, const float* __restrict__ pastv,
    const int* __restrict__ mask)
{
    extern __shared__ __align__(16) float sm[];
    float* Qs = sm;                    // [128][SQ]
    float* Kb = Qs + 128 * SQ;         // [2][64][SQ]
    float* Vs = Kb + 2 * 64 * SQ;      // [64][SV]
    float* Ps = Vs + 64 * SV;          // [128][SP]
    float* pm = Ps + 128 * SP;         // [2][128] partial max / partial l

    const int tid = threadIdx.x;
    const int lane = tid & 31, w = tid >> 5;
    const int wm = w & 7, wn = w >> 3;           // 8 m-slabs x 2 n-slabs
    const int g = lane >> 2, t = lane & 3;
    const int c2 = 2 * t;
    const int qt = blockIdx.x, h = blockIdx.y, b = blockIdx.z;
    const int hkv = h >> 2;
    const int q0 = qt * 128;

    const int row0l = 16 * wm + g;               // warp's q rows
    const int row1l = row0l + 8;

    // cp.async loader indices (64x128 tile, 512 threads, 4 rows apart)
    const int lr = tid >> 5;             // 0..15
    const int lc4 = (tid & 31) << 2;

    // ---- prefetch K tile 0 ----
    {
#pragma unroll
        for (int rr = 0; rr < 4; ++rr) {
            int jg = lr + rr * 16;
            const float* ksrc;
            if (jg < PAST)
                ksrc = pastk + ((size_t)(b * NKV + hkv) * PAST + jg) * HD + lc4;
            else
                ksrc = g_k + (size_t)(b * QL + (jg - PAST)) * (NKV * HD) + hkv * HD + lc4;
            cp_async16(smem_u32(&Kb[(lr + rr * 16) * SQ + lc4]), ksrc);
        }
        asm volatile("cp.async.commit_group;" ::: "memory");
    }

    // ---- load Q tile (pre-rounded) ----
    for (int e = tid; e < 128 * 32; e += 512) {
        int r = e >> 5, c4 = (e & 31) << 2;
        *(float4*)&Qs[r * SQ + c4] =
            *(const float4*)(g_q + (size_t)(b * QL + q0 + r) * HIDN + h * HD + c4);
    }

    float m0 = -1e30f, m1 = -1e30f, l0 = 0.f, l1 = 0.f;
    float o_[8][4];
#pragma unroll
    for (int nt = 0; nt < 8; ++nt)
#pragma unroll
        for (int e = 0; e < 4; ++e) o_[nt][e] = 0.f;

    const uint32_t* Qu = (const uint32_t*)Qs;
    const uint32_t* Vu = (const uint32_t*)Vs;
    const uint32_t* Pu = (const uint32_t*)Ps;

    const int rA0 = row0l * SQ;
    const int rA1 = row1l * SQ;
    const int pA0 = row0l * SP;
    const int pA1 = row1l * SP;

    for (int kt = 0; kt < NKT; ++kt) {
        const int kv0 = kt * 64;
        const int cur = kt & 1;
        const uint32_t* Ku = (const uint32_t*)(Kb + cur * 64 * SQ);

        // ---- issue V_kt ----
#pragma unroll
        for (int rr = 0; rr < 4; ++rr) {
            int jg = kv0 + lr + rr * 16;
            const float* vsrc;
            if (jg < PAST)
                vsrc = pastv + ((size_t)(b * NKV + hkv) * PAST + jg) * HD + lc4;
            else
                vsrc = g_v + (size_t)(b * QL + (jg - PAST)) * (NKV * HD) + hkv * HD + lc4;
            cp_async16(smem_u32(&Vs[(lr + rr * 16) * SV + lc4]), vsrc);
        }
        asm volatile("cp.async.commit_group;" ::: "memory");

        // ---- issue K_{kt+1} (empty group on last iter) ----
        if (kt + 1 < NKT) {
            float* Knxt = Kb + (cur ^ 1) * 64 * SQ;
#pragma unroll
            for (int rr = 0; rr < 4; ++rr) {
                int jg = kv0 + 64 + lr + rr * 16;
                const float* ksrc;
                if (jg < PAST)
                    ksrc = pastk + ((size_t)(b * NKV + hkv) * PAST + jg) * HD + lc4;
                else
                    ksrc = g_k + (size_t)(b * QL + (jg - PAST)) * (NKV * HD) + hkv * HD + lc4;
                cp_async16(smem_u32(&Knxt[(lr + rr * 16) * SQ + lc4]), ksrc);
            }
        }
        asm volatile("cp.async.commit_group;" ::: "memory");

        // ---- mask regs (warp's 32-col slab) ----
        int2 mv[4];
#pragma unroll
        for (int nt = 0; nt < 4; ++nt)
            mv[nt] = *(const int2*)&mask[b * SKV + kv0 + 32 * wn + 8 * nt + c2];

        // ---- wait K_kt (V_kt + K_{kt+1} stay pending) ----
        asm volatile("cp.async.wait_group 2;" ::: "memory");
        __syncthreads();

        // ---- S = Q K^T (warp: 16 x 32) ----
        float s[4][4];
#pragma unroll
        for (int nt = 0; nt < 4; ++nt)
#pragma unroll
            for (int e = 0; e < 4; ++e) s[nt][e] = 0.f;

#pragma unroll
        for (int ks = 0; ks < 128; ks += 8) {
            uint32_t a[4] = {Qu[rA0 + ks + t], Qu[rA1 + ks + t],
                             Qu[rA0 + ks + t + 4], Qu[rA1 + ks + t + 4]};
#pragma unroll
            for (int nt = 0; nt < 4; ++nt) {
                uint32_t bb[2] = {Ku[(32 * wn + 8 * nt + g) * SQ + ks + t],
                                  Ku[(32 * wn + 8 * nt + g) * SQ + ks + t + 4]};
                mma_tf32_16n8k8(s[nt], a, bb);
            }
        }

        // ---- mask + warp-partial row max ----
        float rm0 = -1e30f, rm1 = -1e30f;
#pragma unroll
        for (int nt = 0; nt < 4; ++nt) {
            float mk0 = (mv[nt].x == 0) ? 0.0f : -1e9f;
            float mk1 = (mv[nt].y == 0) ? 0.0f : -1e9f;
            s[nt][0] += mk0; s[nt][1] += mk1;
            s[nt][2] += mk0; s[nt][3] += mk1;
            rm0 = fmaxf(rm0, fmaxf(s[nt][0], s[nt][1]));
            rm1 = fmaxf(rm1, fmaxf(s[nt][2], s[nt][3]));
        }
        rm0 = fmaxf(rm0, __shfl_xor_sync(0xffffffffu, rm0, 1));
        rm0 = fmaxf(rm0, __shfl_xor_sync(0xffffffffu, rm0, 2));
        rm1 = fmaxf(rm1, __shfl_xor_sync(0xffffffffu, rm1, 1));
        rm1 = fmaxf(rm1, __shfl_xor_sync(0xffffffffu, rm1, 2));

        if (t == 0) {
            pm[wn * 128 + 16 * wm + g]     = rm0;
            pm[wn * 128 + 16 * wm + 8 + g] = rm1;
        }
        __syncthreads();
        float rmA0 = fmaxf(pm[16 * wm + g],     pm[128 + 16 * wm + g]);
        float rmA1 = fmaxf(pm[16 * wm + 8 + g], pm[128 + 16 * wm + 8 + g]);

        float mn0 = fmaxf(m0, rmA0), mn1 = fmaxf(m1, rmA1);
        float corr0 = __expf(m0 - mn0), corr1 = __expf(m1 - mn1);
        float rs0 = 0.f, rs1 = 0.f;
#pragma unroll
        for (int nt = 0; nt < 4; ++nt) {
            float p0 = __expf(s[nt][0] - mn0);
            float p1 = __expf(s[nt][1] - mn0);
            float p2 = __expf(s[nt][2] - mn1);
            float p3 = __expf(s[nt][3] - mn1);
            rs0 += p0 + p1; rs1 += p2 + p3;
            Ps[pA0 + 32 * wn + 8 * nt + c2]     = f2tf32f(p0);
            Ps[pA0 + 32 * wn + 8 * nt + c2 + 1] = f2tf32f(p1);
            Ps[pA1 + 32 * wn + 8 * nt + c2]     = f2tf32f(p2);
            Ps[pA1 + 32 * wn + 8 * nt + c2 + 1] = f2tf32f(p3);
        }
        rs0 += __shfl_xor_sync(0xffffffffu, rs0, 1);
        rs0 += __shfl_xor_sync(0xffffffffu, rs0, 2);
        rs1 += __shfl_xor_sync(0xffffffffu, rs1, 1);
        rs1 += __shfl_xor_sync(0xffffffffu, rs1, 2);

        l0 = l0 * corr0 + rs0; m0 = mn0;   // per-warp partial l (half the cols)
        l1 = l1 * corr1 + rs1; m1 = mn1;
#pragma unroll
        for (int nt = 0; nt < 8; ++nt) {
            o_[nt][0] *= corr0; o_[nt][1] *= corr0;
            o_[nt][2] *= corr1; o_[nt][3] *= corr1;
        }

        // ---- P visible to all warps; V_kt complete (K_{kt+1} pending) ----
        asm volatile("cp.async.wait_group 1;" ::: "memory");
        __syncthreads();

        // ---- O += P V (warp: 16 x 64, k = 64) ----
#pragma unroll
        for (int ks = 0; ks < 64; ks += 8) {
            uint32_t a[4] = {Pu[pA0 + ks + t], Pu[pA1 + ks + t],
                             Pu[pA0 + ks + t + 4], Pu[pA1 + ks + t + 4]};
#pragma unroll
            for (int nt = 0; nt < 8; ++nt) {
                uint32_t bb[2] = {Vu[(ks + t) * SV + 64 * wn + 8 * nt + g],
                                  Vu[(ks + t + 4) * SV + 64 * wn + 8 * nt + g]};
                mma_tf32_16n8k8(o_[nt], a, bb);
            }
        }
        __syncthreads();   // Vs/Ps/pm free for next iteration
    }

    // ---- combine per-warp partial l across the n-pair ----
    if (t == 0) {
        pm[wn * 128 + 16 * wm + g]     = l0;
        pm[wn * 128 + 16 * wm + 8 + g] = l1;
    }
    __syncthreads();
    float lt0 = pm[16 * wm + g]     + pm[128 + 16 * wm + g];
    float lt1 = pm[16 * wm + 8 + g] + pm[128 + 16 * wm + 8 + g];

    // ---- epilogue: normalize, round to tf32 for the O-projection ----
    float i0 = 1.0f / lt0, i1 = 1.0f / lt1;
    size_t grow0 = (size_t)(b * QL + q0 + 16 * wm + g);
    size_t grow1 = grow0 + 8;
#pragma unroll
    for (int nt = 0; nt < 8; ++nt) {
        int col = h * HD + 64 * wn + 8 * nt + c2;
        float2 v0 = {f2tf32f(o_[nt][0] * i0), f2tf32f(o_[nt][1] * i0)};
        float2 v1 = {f2tf32f(o_[nt][2] * i1), f2tf32f(o_[nt][3] * i1)};
        *(float2*)&g_att[grow0 * HIDN + col] = v0;
        *(float2*)&g_att[grow1 * HIDN + col] = v1;
    }
}

// ======================================================================
extern "C" void kernel_launch(void* const* d_in, const int* in_sizes, int n_in,
                              void* d_out, int out_size)
{
    (void)in_sizes; (void)n_in; (void)out_size;
    const float* hidden = (const float*)d_in[0];
    const float* pastk  = (const float*)d_in[1];
    const float* pastv  = (const float*)d_in[2];
    const int*   mask   = (const int*)  d_in[3];
    const float* Wq = (const float*)d_in[4];
    const float* bq = (const float*)d_in[5];
    const float* Wk = (const float*)d_in[6];
    const float* bk = (const float*)d_in[7];
    const float* Wv = (const float*)d_in[8];
    const float* bv = (const float*)d_in[9];
    const float* Wo = (const float*)d_in[10];
    const float* bo = (const float*)d_in[11];
    float* out = (float*)d_out;

    float *qp, *kp, *vp, *ap, *thid, *twq, *twk, *twv, *two, *tpk, *tpv;
    cudaGetSymbolAddress((void**)&qp, g_q);
    cudaGetSymbolAddress((void**)&kp, g_k);
    cudaGetSymbolAddress((void**)&vp, g_v);
    cudaGetSymbolAddress((void**)&ap, g_att);
    cudaGetSymbolAddress((void**)&thid, t_hid);
    cudaGetSymbolAddress((void**)&twq, t_wq);
    cudaGetSymbolAddress((void**)&twk, t_wk);
    cudaGetSymbolAddress((void**)&twv, t_wv);
    cudaGetSymbolAddress((void**)&two, t_wo);
    cudaGetSymbolAddress((void**)&tpk, t_pk);
    cudaGetSymbolAddress((void**)&tpv, t_pv);

    cudaFuncSetAttribute(attn_mma, cudaFuncAttributeMaxDynamicSharedMemorySize, ATTN2_SMEM);

    const float alpha_q = 0.08838834764831845f;  // SCALING / sqrt(HEAD_DIM)

    // ---- pre-round harness inputs to tf32 (RNA), once ----
    auto rr = [&](const float* src, float* dst, size_t n) {
        int n4 = (int)(n / 4);
        round_tf32<<<(n4 + 255) / 256, 256>>>((const float4*)src, (float4*)dst, n4);
    };
    rr(hidden, thid, (size_t)MROWS * HIDN);
    rr(Wq, twq, (size_t)HIDN * HIDN);
    rr(Wk, twk, (size_t)(NKV * HD) * HIDN);
    rr(Wv, twv, (size_t)(NKV * HD) * HIDN);
    rr(Wo, two, (size_t)HIDN * HIDN);
    rr(pastk, tpk, (size_t)BB * NKV * PAST * HD);
    rr(pastv, tpv, (size_t)BB * NKV * PAST * HD);

    // ---- QKV projections ----
    gemm_mma<<<dim3(HIDN / 128, MROWS / 128), 256>>>(thid, twq, bq, qp, HIDN, HIDN, alpha_q, 1);
    gemm_mma<<<dim3((NKV * HD) / 128, MROWS / 128), 256>>>(thid, twk, bk, kp, NKV * HD, HIDN, 1.0f, 1);
    gemm_mma<<<dim3((NKV * HD) / 128, MROWS / 128), 256>>>(thid, twv, bv, vp, NKV * HD, HIDN, 1.0f, 1);

    // ---- attention (512 threads, 16 warps) ----
    attn_mma<<<dim3(QL / 128, NH, BB), 512, ATTN2_SMEM>>>(tpk, tpv, mask);

    // ---- output projection ----
    gemm_mma<<<dim3(HIDN / 128, MROWS / 128), 256>>>(ap, two, bo, out, HIDN, HIDN, 1.0f, 0);
}